// round 6
// baseline (speedup 1.0000x reference)
#include <cuda_runtime.h>
#include <math.h>

#define Bq 64
#define Sq 256
#define Hq 512
#define G4 2048
#define Wq 512
#define NBLK 128u

// ---------------- scratch ----------------
__device__ float d_WihT_enc[Sq * G4];
__device__ float d_WihT_dec[Sq * G4];
__device__ float d_WhhT_enc[Hq * G4];
__device__ float d_WhhT_dec[Hq * G4];
__device__ float d_w1T[Hq * Wq];
__device__ float d_w2T[Hq * Wq];
__device__ float d_bias_enc[G4];
__device__ float d_bias_dec[G4];
__device__ float d_Xenc[(size_t)Bq * Sq * G4];
__device__ float d_Xdec[(size_t)Bq * Sq * G4];
__device__ float d_h[Bq * Hq];
__device__ float d_c[Bq * Hq];
__device__ float d_enc_out[(size_t)Bq * Sq * Hq]; // [B,S,H]
__device__ float d_e1[(size_t)Bq * Sq * Wq];      // [B,S,W]
__device__ float d_gpart[4 * Bq * G4];
__device__ float d_hw2part[8 * Bq * Wq];

// ---------------- distributed flag-array grid barrier ----------------
__device__ unsigned g_flags_enc[NBLK];
__device__ unsigned g_flags_dec[NBLK];

__device__ __forceinline__ void gbar(unsigned* flags, unsigned phase) {
    __syncthreads();
    const int tid = threadIdx.x;
    if (tid == 0) {
        asm volatile("st.release.gpu.u32 [%0], %1;" ::"l"(flags + blockIdx.x),
                     "r"(phase)
                     : "memory");
    }
    if (tid < (int)NBLK) {
        unsigned v;
        do {
            asm volatile("ld.acquire.gpu.u32 %0, [%1];" : "=r"(v) : "l"(flags + tid) : "memory");
        } while (v < phase);
    }
    __syncthreads();
}

// ---------------- math ----------------
__device__ __forceinline__ float ftanh_acc(float x) {   // accurate (cell / recurrence)
    float ax = fabsf(x);
    float e = __expf(-2.f * ax);
    float r = __fdividef(1.f - e, 1.f + e);
    return copysignf(r, x);
}
__device__ __forceinline__ float fsigmoid(float x) {
    return __fdividef(1.f, 1.f + __expf(-x));
}
__device__ __forceinline__ float htanh(float x) {       // HW MUFU.TANH (attention only)
    float y;
    asm("tanh.approx.f32 %0, %1;" : "=f"(y) : "f"(x));
    return y;
}

// ---------------- setup ----------------
__global__ void transpose_k(const float* __restrict__ A, float* __restrict__ At,
                            int R, int C) {
    __shared__ float tile[32][33];
    int c0 = blockIdx.x << 5, r0 = blockIdx.y << 5;
    int tx = threadIdx.x, ty = threadIdx.y;
#pragma unroll
    for (int i = 0; i < 32; i += 8)
        tile[ty + i][tx] = A[(size_t)(r0 + ty + i) * C + c0 + tx];
    __syncthreads();
#pragma unroll
    for (int i = 0; i < 32; i += 8)
        At[(size_t)(c0 + ty + i) * R + r0 + tx] = tile[tx][ty + i];
}

__global__ void prep_small_k(const float* __restrict__ ebih, const float* __restrict__ ebhh,
                             const float* __restrict__ dbih, const float* __restrict__ dbhh) {
    int i = blockIdx.x * 256 + threadIdx.x;
    if (i < G4) {
        d_bias_enc[i] = ebih[i] + ebhh[i];
        d_bias_dec[i] = dbih[i] + dbhh[i];
    }
    if (i < Bq * Hq) {
        d_h[i] = 0.f;
        d_c[i] = 0.f;
    }
    if (i < (int)NBLK) {
        g_flags_enc[i] = 0u;
        g_flags_dec[i] = 0u;
    }
}

// ---------------- big GEMM: BM=BN=128, BK=16, 8x8/thr ----------------
__global__ __launch_bounds__(256) void gemm128_k(const float* __restrict__ A,
                                                 const float* __restrict__ Bm,
                                                 const float* __restrict__ bias,
                                                 float* __restrict__ C, int N, int K) {
    __shared__ float sA[16][136];
    __shared__ float sB[16][136];
    const int bm = blockIdx.y * 128, bn = blockIdx.x * 128;
    const int tid = threadIdx.x;
    const int tx = tid & 15, ty = tid >> 4;
    float acc[8][8] = {};
    for (int k0 = 0; k0 < K; k0 += 16) {
#pragma unroll
        for (int q = 0; q < 2; q++) {
            int f = tid * 2 + q;
            int r = f >> 2, c4 = (f & 3) * 4;
            float4 v = *reinterpret_cast<const float4*>(A + (size_t)(bm + r) * K + k0 + c4);
            sA[c4 + 0][r] = v.x;
            sA[c4 + 1][r] = v.y;
            sA[c4 + 2][r] = v.z;
            sA[c4 + 3][r] = v.w;
        }
#pragma unroll
        for (int q = 0; q < 2; q++) {
            int f = tid * 2 + q;
            int r = f >> 5, c = (f & 31) * 4;
            *reinterpret_cast<float4*>(&sB[r][c]) =
                *reinterpret_cast<const float4*>(Bm + (size_t)(k0 + r) * N + bn + c);
        }
        __syncthreads();
#pragma unroll
        for (int kk = 0; kk < 16; kk++) {
            float a[8], b[8];
            *reinterpret_cast<float4*>(a) = *reinterpret_cast<float4*>(&sA[kk][ty * 8]);
            *reinterpret_cast<float4*>(a + 4) = *reinterpret_cast<float4*>(&sA[kk][ty * 8 + 4]);
            *reinterpret_cast<float4*>(b) = *reinterpret_cast<float4*>(&sB[kk][tx * 8]);
            *reinterpret_cast<float4*>(b + 4) = *reinterpret_cast<float4*>(&sB[kk][tx * 8 + 4]);
#pragma unroll
            for (int i = 0; i < 8; i++)
#pragma unroll
                for (int j = 0; j < 8; j++) acc[i][j] += a[i] * b[j];
        }
        __syncthreads();
    }
#pragma unroll
    for (int i = 0; i < 8; i++)
#pragma unroll
        for (int j = 0; j < 8; j++) {
            int m = bm + ty * 8 + i, n = bn + tx * 8 + j;
            float v = acc[i][j];
            if (bias) v += bias[n];
            C[(size_t)m * N + n] = v;
        }
}

// ---------------- recurrent GEMM tile: out[part][64, n0:n0+64] ----------------
// A (d_h) is step-mutable -> __ldcg (L2-only) to avoid stale L1 across barriers.
__device__ void gemm_tile_dev(const float* __restrict__ A, const float* __restrict__ Bm,
                              float* __restrict__ outp, int N, int n0, int k0, int nk32,
                              int part) {
    __shared__ float sA[32][68];
    __shared__ float sB[32][68];
    const int tid = threadIdx.x;
    const int tr = tid >> 4, tc = tid & 15;
    float acc[4][4] = {};
    for (int kc = 0; kc < nk32; kc++) {
        int kb = k0 + kc * 32;
#pragma unroll
        for (int q = 0; q < 2; q++) {
            int v = tid * 2 + q;                 // 0..511
            int m = v >> 3, kq = (v & 7) * 4;
            float4 av = __ldcg(reinterpret_cast<const float4*>(A + m * Hq + kb + kq));
            sA[kq + 0][m] = av.x;
            sA[kq + 1][m] = av.y;
            sA[kq + 2][m] = av.z;
            sA[kq + 3][m] = av.w;
        }
#pragma unroll
        for (int q = 0; q < 2; q++) {
            int v = tid * 2 + q;                 // 0..511
            int kk = v >> 4, c = (v & 15) * 4;
            *reinterpret_cast<float4*>(&sB[kk][c]) =
                *reinterpret_cast<const float4*>(Bm + (size_t)(kb + kk) * N + n0 + c);
        }
        __syncthreads();
#pragma unroll
        for (int kk = 0; kk < 32; kk++) {
            float a[4], b[4];
            *reinterpret_cast<float4*>(a) = *reinterpret_cast<float4*>(&sA[kk][tr * 4]);
            *reinterpret_cast<float4*>(b) = *reinterpret_cast<float4*>(&sB[kk][tc * 4]);
#pragma unroll
            for (int i = 0; i < 4; i++)
#pragma unroll
                for (int j = 0; j < 4; j++) acc[i][j] += a[i] * b[j];
        }
        __syncthreads();
    }
#pragma unroll
    for (int i = 0; i < 4; i++)
#pragma unroll
        for (int j = 0; j < 4; j++) {
            int m = tr * 4 + i, n = n0 + tc * 4 + j;
            outp[(size_t)(part * Bq + m) * N + n] = acc[i][j];
        }
}

// ---------------- LSTM cell phase ----------------
__device__ void cell_dev(const float* __restrict__ Xpre, int t, bool is_enc) {
    int idx = blockIdx.x * 256 + threadIdx.x;
    int b = idx >> 9, m = idx & 511;
    const float* xp = Xpre + ((size_t)b * Sq + t) * G4;
    float gi = xp[m], gf = xp[m + 512], gg = xp[m + 1024], go = xp[m + 1536];
#pragma unroll
    for (int ks = 0; ks < 4; ks++) {
        const float* gp = d_gpart + (size_t)(ks * Bq + b) * G4;
        gi += __ldcg(gp + m);
        gf += __ldcg(gp + m + 512);
        gg += __ldcg(gp + m + 1024);
        go += __ldcg(gp + m + 1536);
    }
    float cv = d_c[idx];   // written/read by same thread each step -> L1-safe
    float cn = fsigmoid(gf) * cv + fsigmoid(gi) * ftanh_acc(gg);
    float hn = fsigmoid(go) * ftanh_acc(cn);
    d_h[idx] = hn;
    if (is_enc) {
        d_c[idx] = cn;
        d_enc_out[((size_t)b * Sq + t) * Hq + m] = hn;  // [B,S,H]
    }
}

// gates GEMM unit u (0..127): n0=(u>>2)*64, kslice=(u&3)
__device__ __forceinline__ void g_unit(const float* WhhT, int u) {
    gemm_tile_dev(d_h, WhhT, d_gpart, G4, (u >> 2) * 64, (u & 3) * 128, 4, u & 3);
}

// ---------------- persistent encoder ----------------
__global__ __launch_bounds__(256) void enc_persist_k(const float* __restrict__ Xenc) {
    unsigned ph = 0;
    const int blk = blockIdx.x;
    for (int t = 0; t < Sq; t++) {
        g_unit(d_WhhT_enc, blk);
        gbar(g_flags_enc, ++ph);
        cell_dev(Xenc, t, true);
        gbar(g_flags_enc, ++ph);
    }
}

// ---------------- persistent decoder ----------------
__global__ __launch_bounds__(256) void dec_persist_k(const float* __restrict__ Xdec,
                                                     const float* __restrict__ vt,
                                                     float* __restrict__ out) {
    unsigned ph = 0;
    const int blk = blockIdx.x;
    const int tid = threadIdx.x;
    const int lane = tid & 31;
    __shared__ __align__(16) float hw2_s[Wq];
    __shared__ float sc_s[Sq];
    __shared__ float red[256];

    float4 vt4[4];
    if (blk < 64) {
#pragma unroll
        for (int c = 0; c < 4; c++)
            vt4[c] = *reinterpret_cast<const float4*>(vt + (c * 32 + lane) * 4);
    }

    // prologue: gates for t=0 (h = hT from encoder)
    g_unit(d_WhhT_dec, blk);
    gbar(g_flags_dec, ++ph);

    for (int t = 0; t < Sq; t++) {
        // P_C: h_new (c stays cT)
        cell_dev(Xdec, t, false);
        gbar(g_flags_dec, ++ph);

        // P_A: blocks 0..63: hw2 partials = h_new @ w2T; blocks 64..127: G(t+1) units 0..63
        if (blk < 64)
            gemm_tile_dev(d_h, d_w2T, d_hw2part, Wq, (blk >> 3) * 64, (blk & 7) * 64, 2,
                          blk & 7);
        else
            g_unit(d_WhhT_dec, blk - 64);
        gbar(g_flags_dec, ++ph);

        // P_B: blocks 0..63: attention + log_softmax for b=blk; blocks 64..127: G units 64..127
        if (blk < 64) {
            const int b = blk;
            for (int w = tid; w < Wq; w += 256) {
                float s = 0.f;
#pragma unroll
                for (int p = 0; p < 8; p++)
                    s += __ldcg(&d_hw2part[(size_t)(p * Bq + b) * Wq + w]);
                hw2_s[w] = s;
            }
            __syncthreads();
            float4 hv[4];
#pragma unroll
            for (int c = 0; c < 4; c++)
                hv[c] = *reinterpret_cast<float4*>(hw2_s + (c * 32 + lane) * 4);
            int wid = tid >> 5;
            for (int s = wid; s < Sq; s += 8) {
                const float* ep = d_e1 + ((size_t)b * Sq + s) * Wq;
                float sum = 0.f;
#pragma unroll
                for (int c = 0; c < 4; c++) {
                    float4 ev = *reinterpret_cast<const float4*>(ep + (c * 32 + lane) * 4);
                    sum += vt4[c].x * htanh(ev.x + hv[c].x);
                    sum += vt4[c].y * htanh(ev.y + hv[c].y);
                    sum += vt4[c].z * htanh(ev.z + hv[c].z);
                    sum += vt4[c].w * htanh(ev.w + hv[c].w);
                }
#pragma unroll
                for (int off = 16; off; off >>= 1)
                    sum += __shfl_xor_sync(0xffffffffu, sum, off);
                if (lane == 0) sc_s[s] = sum;
            }
            __syncthreads();
            float v = sc_s[tid];
            red[tid] = v;
            __syncthreads();
            for (int st = 128; st; st >>= 1) {
                if (tid < st) red[tid] = fmaxf(red[tid], red[tid + st]);
                __syncthreads();
            }
            float mx = red[0];
            __syncthreads();
            red[tid] = __expf(v - mx);
            __syncthreads();
            for (int st = 128; st; st >>= 1) {
                if (tid < st) red[tid] += red[tid + st];
                __syncthreads();
            }
            float lse = mx + __logf(red[0]);
            out[((size_t)b * Sq + t) * Sq + tid] = v - lse;
        } else {
            g_unit(d_WhhT_dec, blk);   // units 64..127
        }
        gbar(g_flags_dec, ++ph);
    }
}

// ---------------- launch ----------------
extern "C" void kernel_launch(void* const* d_in, const int* in_sizes, int n_in,
                              void* d_out, int out_size) {
    const float* x = (const float*)d_in[0];
    const float* enc_Wih = (const float*)d_in[1];
    const float* enc_Whh = (const float*)d_in[2];
    const float* enc_bih = (const float*)d_in[3];
    const float* enc_bhh = (const float*)d_in[4];
    const float* dec_Wih = (const float*)d_in[5];
    const float* dec_Whh = (const float*)d_in[6];
    const float* dec_bih = (const float*)d_in[7];
    const float* dec_bhh = (const float*)d_in[8];
    const float* w1 = (const float*)d_in[9];
    const float* w2 = (const float*)d_in[10];
    const float* vt = (const float*)d_in[11];
    float* out = (float*)d_out;

    float *WihT_enc, *WihT_dec, *WhhT_enc, *WhhT_dec, *w1T, *w2T;
    float *Xenc, *Xdec, *enc_out, *e1, *bias_e, *bias_d;
    cudaGetSymbolAddress((void**)&WihT_enc, d_WihT_enc);
    cudaGetSymbolAddress((void**)&WihT_dec, d_WihT_dec);
    cudaGetSymbolAddress((void**)&WhhT_enc, d_WhhT_enc);
    cudaGetSymbolAddress((void**)&WhhT_dec, d_WhhT_dec);
    cudaGetSymbolAddress((void**)&w1T, d_w1T);
    cudaGetSymbolAddress((void**)&w2T, d_w2T);
    cudaGetSymbolAddress((void**)&Xenc, d_Xenc);
    cudaGetSymbolAddress((void**)&Xdec, d_Xdec);
    cudaGetSymbolAddress((void**)&enc_out, d_enc_out);
    cudaGetSymbolAddress((void**)&e1, d_e1);
    cudaGetSymbolAddress((void**)&bias_e, d_bias_enc);
    cudaGetSymbolAddress((void**)&bias_d, d_bias_dec);

    dim3 tb(32, 8);
    transpose_k<<<dim3(Sq / 32, G4 / 32), tb>>>(enc_Wih, WihT_enc, G4, Sq);
    transpose_k<<<dim3(Sq / 32, G4 / 32), tb>>>(dec_Wih, WihT_dec, G4, Sq);
    transpose_k<<<dim3(Hq / 32, G4 / 32), tb>>>(enc_Whh, WhhT_enc, G4, Hq);
    transpose_k<<<dim3(Hq / 32, G4 / 32), tb>>>(dec_Whh, WhhT_dec, G4, Hq);
    transpose_k<<<dim3(Hq / 32, Wq / 32), tb>>>(w1, w1T, Wq, Hq);
    transpose_k<<<dim3(Hq / 32, Wq / 32), tb>>>(w2, w2T, Wq, Hq);
    prep_small_k<<<128, 256>>>(enc_bih, enc_bhh, dec_bih, dec_bhh);

    // input projections
    gemm128_k<<<dim3(G4 / 128, (Bq * Sq) / 128), 256>>>(x, WihT_enc, bias_e, Xenc, G4, Sq);
    gemm128_k<<<dim3(G4 / 128, (Bq * Sq) / 128), 256>>>(x, WihT_dec, bias_d, Xdec, G4, Sq);

    // encoder (persistent)
    enc_persist_k<<<NBLK, 256>>>(Xenc);

    // e1 = enc_out @ w1T  (rows = b*S+s -> e1 in [B,S,W])
    gemm128_k<<<dim3(Wq / 128, (Sq * Bq) / 128), 256>>>(enc_out, w1T, (const float*)0, e1,
                                                        Wq, Hq);

    // decoder (persistent)
    dec_persist_k<<<NBLK, 256>>>(Xdec, vt, out);
}

// round 7
// speedup vs baseline: 1.5303x; 1.5303x over previous
#include <cuda_runtime.h>
#include <math.h>

#define Bq 64
#define Sq 256
#define Hq 512
#define G4 2048
#define Wq 512
#define NBLK 128u

// ---------------- scratch ----------------
__device__ float d_WihT_enc[Sq * G4];
__device__ float d_WihT_dec[Sq * G4];
__device__ float d_WhhT_enc[Hq * G4];
__device__ float d_WhhT_dec[Hq * G4];
__device__ float d_w1T[Hq * Wq];
__device__ float d_w2T[Hq * Wq];
__device__ float d_bias_enc[G4];
__device__ float d_bias_dec[G4];
__device__ float d_Xenc[(size_t)Bq * Sq * G4];
__device__ float d_Xdec[(size_t)Bq * Sq * G4];
__device__ float d_h[Bq * Hq];
__device__ float d_c[Bq * Hq];
__device__ float d_enc_out[(size_t)Bq * Sq * Hq]; // [B,S,H]
__device__ float d_e1[(size_t)Bq * Sq * Wq];      // [B,S,W]
__device__ float d_gpart[4 * Bq * G4];
__device__ float d_hw2part[8 * Bq * Wq];

// ---------------- monotonic-counter grid barrier (1 arriver+poller per block) ------
__device__ __align__(128) unsigned g_ctr_enc[32];   // only [0] used; line-isolated
__device__ __align__(128) unsigned g_ctr_dec[32];

__device__ __forceinline__ void gbar_ctr(unsigned* ctr, unsigned target) {
    __syncthreads();
    if (threadIdx.x == 0) {
        unsigned old, one = 1u;
        asm volatile("atom.release.gpu.add.u32 %0, [%1], %2;"
                     : "=r"(old) : "l"(ctr), "r"(one) : "memory");
        unsigned v;
        do {
            asm volatile("ld.acquire.gpu.u32 %0, [%1];" : "=r"(v) : "l"(ctr) : "memory");
        } while (v < target);
    }
    __syncthreads();
}

// ---------------- math ----------------
__device__ __forceinline__ float ftanh_acc(float x) {   // accurate (cell / recurrence)
    float ax = fabsf(x);
    float e = __expf(-2.f * ax);
    float r = __fdividef(1.f - e, 1.f + e);
    return copysignf(r, x);
}
__device__ __forceinline__ float fsigmoid(float x) {
    return __fdividef(1.f, 1.f + __expf(-x));
}
__device__ __forceinline__ float htanh(float x) {       // HW MUFU.TANH (attention only)
    float y;
    asm("tanh.approx.f32 %0, %1;" : "=f"(y) : "f"(x));
    return y;
}

// ---------------- setup ----------------
__global__ void transpose_k(const float* __restrict__ A, float* __restrict__ At,
                            int R, int C) {
    __shared__ float tile[32][33];
    int c0 = blockIdx.x << 5, r0 = blockIdx.y << 5;
    int tx = threadIdx.x, ty = threadIdx.y;
#pragma unroll
    for (int i = 0; i < 32; i += 8)
        tile[ty + i][tx] = A[(size_t)(r0 + ty + i) * C + c0 + tx];
    __syncthreads();
#pragma unroll
    for (int i = 0; i < 32; i += 8)
        At[(size_t)(c0 + ty + i) * R + r0 + tx] = tile[tx][ty + i];
}

__global__ void prep_small_k(const float* __restrict__ ebih, const float* __restrict__ ebhh,
                             const float* __restrict__ dbih, const float* __restrict__ dbhh) {
    int i = blockIdx.x * 256 + threadIdx.x;
    if (i < G4) {
        d_bias_enc[i] = ebih[i] + ebhh[i];
        d_bias_dec[i] = dbih[i] + dbhh[i];
    }
    if (i < Bq * Hq) {
        d_h[i] = 0.f;
        d_c[i] = 0.f;
    }
    if (i < 32) {
        g_ctr_enc[i] = 0u;
        g_ctr_dec[i] = 0u;
    }
}

// ---------------- big GEMM: BM=BN=128, BK=16, 8x8/thr ----------------
__global__ __launch_bounds__(256) void gemm128_k(const float* __restrict__ A,
                                                 const float* __restrict__ Bm,
                                                 const float* __restrict__ bias,
                                                 float* __restrict__ C, int N, int K) {
    __shared__ float sA[16][136];
    __shared__ float sB[16][136];
    const int bm = blockIdx.y * 128, bn = blockIdx.x * 128;
    const int tid = threadIdx.x;
    const int tx = tid & 15, ty = tid >> 4;
    float acc[8][8] = {};
    for (int k0 = 0; k0 < K; k0 += 16) {
#pragma unroll
        for (int q = 0; q < 2; q++) {
            int f = tid * 2 + q;
            int r = f >> 2, c4 = (f & 3) * 4;
            float4 v = *reinterpret_cast<const float4*>(A + (size_t)(bm + r) * K + k0 + c4);
            sA[c4 + 0][r] = v.x;
            sA[c4 + 1][r] = v.y;
            sA[c4 + 2][r] = v.z;
            sA[c4 + 3][r] = v.w;
        }
#pragma unroll
        for (int q = 0; q < 2; q++) {
            int f = tid * 2 + q;
            int r = f >> 5, c = (f & 31) * 4;
            *reinterpret_cast<float4*>(&sB[r][c]) =
                *reinterpret_cast<const float4*>(Bm + (size_t)(k0 + r) * N + bn + c);
        }
        __syncthreads();
#pragma unroll
        for (int kk = 0; kk < 16; kk++) {
            float a[8], b[8];
            *reinterpret_cast<float4*>(a) = *reinterpret_cast<float4*>(&sA[kk][ty * 8]);
            *reinterpret_cast<float4*>(a + 4) = *reinterpret_cast<float4*>(&sA[kk][ty * 8 + 4]);
            *reinterpret_cast<float4*>(b) = *reinterpret_cast<float4*>(&sB[kk][tx * 8]);
            *reinterpret_cast<float4*>(b + 4) = *reinterpret_cast<float4*>(&sB[kk][tx * 8 + 4]);
#pragma unroll
            for (int i = 0; i < 8; i++)
#pragma unroll
                for (int j = 0; j < 8; j++) acc[i][j] += a[i] * b[j];
        }
        __syncthreads();
    }
#pragma unroll
    for (int i = 0; i < 8; i++)
#pragma unroll
        for (int j = 0; j < 8; j++) {
            int m = bm + ty * 8 + i, n = bn + tx * 8 + j;
            float v = acc[i][j];
            if (bias) v += bias[n];
            C[(size_t)m * N + n] = v;
        }
}

// ---------------- recurrent GEMM tile: out[part][64, n0:n0+64] ----------------
// A (d_h) is step-mutable -> __ldcg (L2-only) to avoid stale L1 across barriers.
__device__ void gemm_tile_dev(const float* __restrict__ A, const float* __restrict__ Bm,
                              float* __restrict__ outp, int N, int n0, int k0, int nk32,
                              int part) {
    __shared__ float sA[32][68];
    __shared__ float sB[32][68];
    const int tid = threadIdx.x;
    const int tr = tid >> 4, tc = tid & 15;
    float acc[4][4] = {};
    for (int kc = 0; kc < nk32; kc++) {
        int kb = k0 + kc * 32;
#pragma unroll
        for (int q = 0; q < 2; q++) {
            int v = tid * 2 + q;                 // 0..511
            int m = v >> 3, kq = (v & 7) * 4;
            float4 av = __ldcg(reinterpret_cast<const float4*>(A + m * Hq + kb + kq));
            sA[kq + 0][m] = av.x;
            sA[kq + 1][m] = av.y;
            sA[kq + 2][m] = av.z;
            sA[kq + 3][m] = av.w;
        }
#pragma unroll
        for (int q = 0; q < 2; q++) {
            int v = tid * 2 + q;                 // 0..511
            int kk = v >> 4, c = (v & 15) * 4;
            *reinterpret_cast<float4*>(&sB[kk][c]) =
                *reinterpret_cast<const float4*>(Bm + (size_t)(kb + kk) * N + n0 + c);
        }
        __syncthreads();
#pragma unroll
        for (int kk = 0; kk < 32; kk++) {
            float a[4], b[4];
            *reinterpret_cast<float4*>(a) = *reinterpret_cast<float4*>(&sA[kk][tr * 4]);
            *reinterpret_cast<float4*>(b) = *reinterpret_cast<float4*>(&sB[kk][tc * 4]);
#pragma unroll
            for (int i = 0; i < 4; i++)
#pragma unroll
                for (int j = 0; j < 4; j++) acc[i][j] += a[i] * b[j];
        }
        __syncthreads();
    }
#pragma unroll
    for (int i = 0; i < 4; i++)
#pragma unroll
        for (int j = 0; j < 4; j++) {
            int m = tr * 4 + i, n = n0 + tc * 4 + j;
            outp[(size_t)(part * Bq + m) * N + n] = acc[i][j];
        }
}

// ---------------- LSTM cell phase ----------------
__device__ void cell_dev(const float* __restrict__ Xpre, int t, bool is_enc) {
    int idx = blockIdx.x * 256 + threadIdx.x;
    int b = idx >> 9, m = idx & 511;
    const float* xp = Xpre + ((size_t)b * Sq + t) * G4;
    float gi = xp[m], gf = xp[m + 512], gg = xp[m + 1024], go = xp[m + 1536];
#pragma unroll
    for (int ks = 0; ks < 4; ks++) {
        const float* gp = d_gpart + (size_t)(ks * Bq + b) * G4;
        gi += __ldcg(gp + m);
        gf += __ldcg(gp + m + 512);
        gg += __ldcg(gp + m + 1024);
        go += __ldcg(gp + m + 1536);
    }
    float cv = d_c[idx];   // written/read by same thread each step -> L1-safe
    float cn = fsigmoid(gf) * cv + fsigmoid(gi) * ftanh_acc(gg);
    float hn = fsigmoid(go) * ftanh_acc(cn);
    d_h[idx] = hn;
    if (is_enc) {
        d_c[idx] = cn;
        d_enc_out[((size_t)b * Sq + t) * Hq + m] = hn;  // [B,S,H]
    }
}

// gates GEMM unit u (0..127): n0=(u>>2)*64, kslice=(u&3)
__device__ __forceinline__ void g_unit(const float* WhhT, int u) {
    gemm_tile_dev(d_h, WhhT, d_gpart, G4, (u >> 2) * 64, (u & 3) * 128, 4, u & 3);
}

// ---------------- persistent encoder ----------------
__global__ __launch_bounds__(256) void enc_persist_k(const float* __restrict__ Xenc) {
    unsigned ph = 0;
    const int blk = blockIdx.x;
    for (int t = 0; t < Sq; t++) {
        g_unit(d_WhhT_enc, blk);
        gbar_ctr(g_ctr_enc, (++ph) * NBLK);
        cell_dev(Xenc, t, true);
        gbar_ctr(g_ctr_enc, (++ph) * NBLK);
    }
}

// ---------------- persistent decoder ----------------
__global__ __launch_bounds__(256) void dec_persist_k(const float* __restrict__ Xdec,
                                                     const float* __restrict__ vt,
                                                     float* __restrict__ out) {
    unsigned ph = 0;
    const int blk = blockIdx.x;
    const int tid = threadIdx.x;
    const int lane = tid & 31;
    __shared__ __align__(16) float hw2_s[Wq];
    __shared__ float sc_s[Sq];
    __shared__ float red[256];

    float4 vt4[4];
    if (blk < 64) {
#pragma unroll
        for (int c = 0; c < 4; c++)
            vt4[c] = *reinterpret_cast<const float4*>(vt + (c * 32 + lane) * 4);
    }

    // prologue: gates for t=0 (h = hT from encoder)
    g_unit(d_WhhT_dec, blk);
    gbar_ctr(g_ctr_dec, (++ph) * NBLK);

    for (int t = 0; t < Sq; t++) {
        // P_C: h_new (c stays cT)
        cell_dev(Xdec, t, false);
        gbar_ctr(g_ctr_dec, (++ph) * NBLK);

        // P_A: blocks 0..63: hw2 partials = h_new @ w2T; blocks 64..127: G(t+1) units 0..63
        if (blk < 64)
            gemm_tile_dev(d_h, d_w2T, d_hw2part, Wq, (blk >> 3) * 64, (blk & 7) * 64, 2,
                          blk & 7);
        else
            g_unit(d_WhhT_dec, blk - 64);
        gbar_ctr(g_ctr_dec, (++ph) * NBLK);

        // P_B: blocks 0..63: attention + log_softmax for b=blk; blocks 64..127: G units 64..127
        if (blk < 64) {
            const int b = blk;
            for (int w = tid; w < Wq; w += 256) {
                float s = 0.f;
#pragma unroll
                for (int p = 0; p < 8; p++)
                    s += __ldcg(&d_hw2part[(size_t)(p * Bq + b) * Wq + w]);
                hw2_s[w] = s;
            }
            __syncthreads();
            float4 hv[4];
#pragma unroll
            for (int c = 0; c < 4; c++)
                hv[c] = *reinterpret_cast<float4*>(hw2_s + (c * 32 + lane) * 4);
            int wid = tid >> 5;
            for (int s = wid; s < Sq; s += 8) {
                const float* ep = d_e1 + ((size_t)b * Sq + s) * Wq;
                float sum = 0.f;
#pragma unroll
                for (int c = 0; c < 4; c++) {
                    float4 ev = *reinterpret_cast<const float4*>(ep + (c * 32 + lane) * 4);
                    sum += vt4[c].x * htanh(ev.x + hv[c].x);
                    sum += vt4[c].y * htanh(ev.y + hv[c].y);
                    sum += vt4[c].z * htanh(ev.z + hv[c].z);
                    sum += vt4[c].w * htanh(ev.w + hv[c].w);
                }
#pragma unroll
                for (int off = 16; off; off >>= 1)
                    sum += __shfl_xor_sync(0xffffffffu, sum, off);
                if (lane == 0) sc_s[s] = sum;
            }
            __syncthreads();
            float v = sc_s[tid];
            red[tid] = v;
            __syncthreads();
            for (int st = 128; st; st >>= 1) {
                if (tid < st) red[tid] = fmaxf(red[tid], red[tid + st]);
                __syncthreads();
            }
            float mx = red[0];
            __syncthreads();
            red[tid] = __expf(v - mx);
            __syncthreads();
            for (int st = 128; st; st >>= 1) {
                if (tid < st) red[tid] += red[tid + st];
                __syncthreads();
            }
            float lse = mx + __logf(red[0]);
            out[((size_t)b * Sq + t) * Sq + tid] = v - lse;
        } else {
            g_unit(d_WhhT_dec, blk);   // units 64..127
        }
        gbar_ctr(g_ctr_dec, (++ph) * NBLK);
    }
}

// ---------------- launch ----------------
extern "C" void kernel_launch(void* const* d_in, const int* in_sizes, int n_in,
                              void* d_out, int out_size) {
    const float* x = (const float*)d_in[0];
    const float* enc_Wih = (const float*)d_in[1];
    const float* enc_Whh = (const float*)d_in[2];
    const float* enc_bih = (const float*)d_in[3];
    const float* enc_bhh = (const float*)d_in[4];
    const float* dec_Wih = (const float*)d_in[5];
    const float* dec_Whh = (const float*)d_in[6];
    const float* dec_bih = (const float*)d_in[7];
    const float* dec_bhh = (const float*)d_in[8];
    const float* w1 = (const float*)d_in[9];
    const float* w2 = (const float*)d_in[10];
    const float* vt = (const float*)d_in[11];
    float* out = (float*)d_out;

    float *WihT_enc, *WihT_dec, *WhhT_enc, *WhhT_dec, *w1T, *w2T;
    float *Xenc, *Xdec, *enc_out, *e1, *bias_e, *bias_d;
    cudaGetSymbolAddress((void**)&WihT_enc, d_WihT_enc);
    cudaGetSymbolAddress((void**)&WihT_dec, d_WihT_dec);
    cudaGetSymbolAddress((void**)&WhhT_enc, d_WhhT_enc);
    cudaGetSymbolAddress((void**)&WhhT_dec, d_WhhT_dec);
    cudaGetSymbolAddress((void**)&w1T, d_w1T);
    cudaGetSymbolAddress((void**)&w2T, d_w2T);
    cudaGetSymbolAddress((void**)&Xenc, d_Xenc);
    cudaGetSymbolAddress((void**)&Xdec, d_Xdec);
    cudaGetSymbolAddress((void**)&enc_out, d_enc_out);
    cudaGetSymbolAddress((void**)&e1, d_e1);
    cudaGetSymbolAddress((void**)&bias_e, d_bias_enc);
    cudaGetSymbolAddress((void**)&bias_d, d_bias_dec);

    dim3 tb(32, 8);
    transpose_k<<<dim3(Sq / 32, G4 / 32), tb>>>(enc_Wih, WihT_enc, G4, Sq);
    transpose_k<<<dim3(Sq / 32, G4 / 32), tb>>>(dec_Wih, WihT_dec, G4, Sq);
    transpose_k<<<dim3(Hq / 32, G4 / 32), tb>>>(enc_Whh, WhhT_enc, G4, Hq);
    transpose_k<<<dim3(Hq / 32, G4 / 32), tb>>>(dec_Whh, WhhT_dec, G4, Hq);
    transpose_k<<<dim3(Hq / 32, Wq / 32), tb>>>(w1, w1T, Wq, Hq);
    transpose_k<<<dim3(Hq / 32, Wq / 32), tb>>>(w2, w2T, Wq, Hq);
    prep_small_k<<<128, 256>>>(enc_bih, enc_bhh, dec_bih, dec_bhh);

    // input projections
    gemm128_k<<<dim3(G4 / 128, (Bq * Sq) / 128), 256>>>(x, WihT_enc, bias_e, Xenc, G4, Sq);
    gemm128_k<<<dim3(G4 / 128, (Bq * Sq) / 128), 256>>>(x, WihT_dec, bias_d, Xdec, G4, Sq);

    // encoder (persistent)
    enc_persist_k<<<NBLK, 256>>>(Xenc);

    // e1 = enc_out @ w1T  (rows = b*S+s -> e1 in [B,S,W])
    gemm128_k<<<dim3(Wq / 128, (Sq * Bq) / 128), 256>>>(enc_out, w1T, (const float*)0, e1,
                                                        Wq, Hq);

    // decoder (persistent)
    dec_persist_k<<<NBLK, 256>>>(Xdec, vt, out);
}